// round 5
// baseline (speedup 1.0000x reference)
#include <cuda_runtime.h>
#include <cuda_bf16.h>
#include <cstdint>

// Problem constants (fixed shapes for this problem instance).
#define NN 50000
#define DD 256
#define EE 400000

// ---------------- device scratch (no allocations allowed) ----------------
__device__ float g_h[NN * DD];        // h = feat @ Wsum  (51.2 MB, L2-resident)
__device__ float g_W[DD * DD];        // (W0+W1+W2)/3
__device__ int   g_deg[3][NN];
__device__ int   g_off[3][NN];
__device__ int   g_cur[3][NN];
__device__ int   g_csr[3][EE];

// ---------------- tiny kernels ----------------
__global__ void zero_kernel() {
    int i = blockIdx.x * blockDim.x + threadIdx.x;
    if (i < 3 * NN) {
        (&g_deg[0][0])[i] = 0;
        (&g_cur[0][0])[i] = 0;
    }
}

__global__ void wsum_kernel(const float* __restrict__ W0,
                            const float* __restrict__ W1,
                            const float* __restrict__ W2) {
    int i = blockIdx.x * blockDim.x + threadIdx.x;
    if (i < DD * DD)
        g_W[i] = (W0[i] + W1[i] + W2[i]) * (1.0f / 3.0f);
}

__global__ void deg_kernel(const int* __restrict__ d0,
                           const int* __restrict__ d1,
                           const int* __restrict__ d2, int E) {
    int i = blockIdx.x * blockDim.x + threadIdx.x;
    if (i >= 3 * E) return;
    int r = i / E;
    int e = i - r * E;
    const int* dp = (r == 0) ? d0 : (r == 1) ? d1 : d2;
    atomicAdd(&g_deg[r][dp[e]], 1);
}

// One block per relation: segmented exclusive scan of degrees -> CSR offsets.
__global__ void scan_kernel(int n) {
    int r = blockIdx.x;           // 0..2
    int tid = threadIdx.x;        // 0..1023
    const int* deg = g_deg[r];
    int* off = g_off[r];
    int per = (n + 1023) >> 10;   // elements per thread (contiguous chunk)
    int a0 = tid * per;
    int s = 0;
    for (int i = 0; i < per; i++) {
        int idx = a0 + i;
        if (idx < n) s += deg[idx];
    }
    __shared__ int sh[1024];
    sh[tid] = s;
    __syncthreads();
    // Hillis-Steele inclusive scan
    for (int o = 1; o < 1024; o <<= 1) {
        int t = (tid >= o) ? sh[tid - o] : 0;
        __syncthreads();
        sh[tid] += t;
        __syncthreads();
    }
    int run = sh[tid] - s;        // exclusive prefix for this chunk
    for (int i = 0; i < per; i++) {
        int idx = a0 + i;
        if (idx < n) { off[idx] = run; run += deg[idx]; }
    }
}

__global__ void fill_kernel(const int* __restrict__ s0, const int* __restrict__ d0,
                            const int* __restrict__ s1, const int* __restrict__ d1,
                            const int* __restrict__ s2, const int* __restrict__ d2,
                            int E) {
    int i = blockIdx.x * blockDim.x + threadIdx.x;
    if (i >= 3 * E) return;
    int r = i / E;
    int e = i - r * E;
    const int* sp = (r == 0) ? s0 : (r == 1) ? s1 : s2;
    const int* dp = (r == 0) ? d0 : (r == 1) ? d1 : d2;
    int dst = dp[e];
    int pos = g_off[r][dst] + atomicAdd(&g_cur[r][dst], 1);
    g_csr[r][pos] = sp[e];
}

// ---------------- SGEMM: g_h[M,256] = A[M,256] @ g_W[256,256] ----------------
// 128x128 block tile, BK=16, 256 threads, 8x8 per-thread microtile.
__global__ __launch_bounds__(256, 2)
void gemm_kernel(const float* __restrict__ A, int M) {
    const int K = DD;
    __shared__ float As[16][128];   // transposed A tile: As[k][m]
    __shared__ float Bs[16][128];   // Bs[k][n]

    int tid = threadIdx.x;
    int tx = tid & 15;              // 0..15 (n groups)
    int ty = tid >> 4;              // 0..15 (m groups)
    int rowBase = blockIdx.x * 128;
    int colBase = blockIdx.y * 128;

    float acc[8][8];
#pragma unroll
    for (int i = 0; i < 8; i++)
#pragma unroll
        for (int j = 0; j < 8; j++) acc[i][j] = 0.f;

    for (int k0 = 0; k0 < K; k0 += 16) {
        // Load A tile (128x16): 512 float4s, 2 per thread.
#pragma unroll
        for (int l = 0; l < 2; l++) {
            int f = tid + l * 256;      // 0..511
            int ar = f >> 2;            // 0..127 (m)
            int ac = (f & 3) * 4;       // 0,4,8,12 (k)
            float4 v = make_float4(0.f, 0.f, 0.f, 0.f);
            int grow = rowBase + ar;
            if (grow < M)
                v = *(const float4*)&A[(size_t)grow * K + k0 + ac];
            As[ac + 0][ar] = v.x;
            As[ac + 1][ar] = v.y;
            As[ac + 2][ar] = v.z;
            As[ac + 3][ar] = v.w;
        }
        // Load B tile (16x128): 512 float4s, 2 per thread.
#pragma unroll
        for (int l = 0; l < 2; l++) {
            int f = tid + l * 256;
            int br = f >> 5;            // 0..15 (k)
            int bc = (f & 31) * 4;      // 0..124 (n)
            float4 v = *(const float4*)&g_W[(size_t)(k0 + br) * DD + colBase + bc];
            *(float4*)&Bs[br][bc] = v;
        }
        __syncthreads();
#pragma unroll
        for (int kk = 0; kk < 16; kk++) {
            float ra[8], rb[8];
            float4 a0v = *(const float4*)&As[kk][ty * 8];
            float4 a1v = *(const float4*)&As[kk][ty * 8 + 4];
            float4 b0v = *(const float4*)&Bs[kk][tx * 8];
            float4 b1v = *(const float4*)&Bs[kk][tx * 8 + 4];
            ra[0] = a0v.x; ra[1] = a0v.y; ra[2] = a0v.z; ra[3] = a0v.w;
            ra[4] = a1v.x; ra[5] = a1v.y; ra[6] = a1v.z; ra[7] = a1v.w;
            rb[0] = b0v.x; rb[1] = b0v.y; rb[2] = b0v.z; rb[3] = b0v.w;
            rb[4] = b1v.x; rb[5] = b1v.y; rb[6] = b1v.z; rb[7] = b1v.w;
#pragma unroll
            for (int i = 0; i < 8; i++)
#pragma unroll
                for (int j = 0; j < 8; j++)
                    acc[i][j] = fmaf(ra[i], rb[j], acc[i][j]);
        }
        __syncthreads();
    }
    // Store
#pragma unroll
    for (int i = 0; i < 8; i++) {
        int grow = rowBase + ty * 8 + i;
        if (grow < M) {
#pragma unroll
            for (int j = 0; j < 8; j += 4) {
                float4 v = make_float4(acc[i][j], acc[i][j + 1], acc[i][j + 2], acc[i][j + 3]);
                *(float4*)&g_h[(size_t)grow * DD + colBase + tx * 8 + j] = v;
            }
        }
    }
}

// ---------------- gather + cross-relation mean + relu + LayerNorm ----------------
// One block (256 threads) per destination node; thread t owns feature dim t.
__global__ __launch_bounds__(256)
void agg_ln_kernel(const float* __restrict__ gamma,
                   const float* __restrict__ beta,
                   float* __restrict__ out, int n) {
    int v = blockIdx.x;
    if (v >= n) return;
    int tid = threadIdx.x;

    __shared__ int es[128];
    float acc = 0.f;

#pragma unroll
    for (int r = 0; r < 3; r++) {
        int dg = g_deg[r][v];          // uniform across block
        if (dg == 0) continue;
        int o = g_off[r][v];
        float accR = 0.f;
        for (int base = 0; base < dg; base += 128) {
            int cnt = min(128, dg - base);
            if (tid < cnt) es[tid] = g_csr[r][o + base + tid];
            __syncthreads();
#pragma unroll 4
            for (int i = 0; i < cnt; i++) {
                const float* hp = g_h + (size_t)es[i] * DD;
                accR += hp[tid];
            }
            __syncthreads();
        }
        acc += accR * (1.0f / (3.0f * (float)dg));
    }

    float x = fmaxf(acc, 0.f);

    // block reduce sum & sumsq over 256 lanes
    float s1 = x, s2 = x * x;
#pragma unroll
    for (int o = 16; o > 0; o >>= 1) {
        s1 += __shfl_xor_sync(0xFFFFFFFFu, s1, o);
        s2 += __shfl_xor_sync(0xFFFFFFFFu, s2, o);
    }
    __shared__ float w1[8], w2[8];
    int wid = tid >> 5, lane = tid & 31;
    if (lane == 0) { w1[wid] = s1; w2[wid] = s2; }
    __syncthreads();
    s1 = 0.f; s2 = 0.f;
#pragma unroll
    for (int i = 0; i < 8; i++) { s1 += w1[i]; s2 += w2[i]; }

    float mean = s1 * (1.0f / 256.0f);
    float var = s2 * (1.0f / 256.0f) - mean * mean;
    var = fmaxf(var, 0.f);
    float inv = rsqrtf(var + 1e-5f);
    out[(size_t)v * DD + tid] = (x - mean) * inv * gamma[tid] + beta[tid];
}

// ---------------- launch ----------------
extern "C" void kernel_launch(void* const* d_in, const int* in_sizes, int n_in,
                              void* d_out, int out_size) {
    const float* feat  = (const float*)d_in[0];
    const float* W0    = (const float*)d_in[1];
    const float* W1    = (const float*)d_in[2];
    const float* W2    = (const float*)d_in[3];
    // d_in[4..6] = a0,a1,a2 : softmax over size-1 tensors -> exactly 1/3 weights; unused.
    const float* gamma = (const float*)d_in[7];
    const float* beta  = (const float*)d_in[8];
    const int* src0 = (const int*)d_in[9];
    const int* dst0 = (const int*)d_in[10];
    const int* src1 = (const int*)d_in[11];
    const int* dst1 = (const int*)d_in[12];
    const int* src2 = (const int*)d_in[13];
    const int* dst2 = (const int*)d_in[14];

    int N = in_sizes[0] / DD;     // 50000
    int E = in_sizes[9];          // 400000

    // CSR build chain
    zero_kernel<<<(3 * NN + 255) / 256, 256>>>();
    wsum_kernel<<<(DD * DD + 255) / 256, 256>>>(W0, W1, W2);
    deg_kernel<<<(3 * E + 255) / 256, 256>>>(dst0, dst1, dst2, E);
    scan_kernel<<<3, 1024>>>(N);
    fill_kernel<<<(3 * E + 255) / 256, 256>>>(src0, dst0, src1, dst1, src2, dst2, E);

    // h = feat @ (W0+W1+W2)/3
    dim3 ggrid((N + 127) / 128, DD / 128);
    gemm_kernel<<<ggrid, 256>>>(feat, N);

    // gather + mean + relu + LN
    agg_ln_kernel<<<N, 256>>>(gamma, beta, (float*)d_out, N);
}